// round 13
// baseline (speedup 1.0000x reference)
#include <cuda_runtime.h>
#include <cuda.h>
#include <cuda_fp16.h>
#include <cstdint>

// ============================================================================
// Feature gate: tcgen05 exists only on the sm_103a pass (proven live by
// rounds 3-12). mma.sync / FMA fallbacks retained, gated by g_has_tc.
// ============================================================================
#if defined(__CUDA_ARCH__) && defined(__CUDA_ARCH_FEAT_SM103_ALL)
#define HAS_TC 1
#else
#define HAS_TC 0
#endif

// ============================================================================
// Problem constants
// ============================================================================
#define IN_DIM   4096
#define OUT_DIM  4096
#define RANK     64
#define M_TOTAL  16384            // 4 * 4096 rows of x

#define NKG      64               // K groups of 64 fp16 columns

// ---- tcgen05 main GEMM: 256x256 CTA tile, single fp16 product ----
#define TILE_M   256
#define TILE_N   256
#define TILE_BYTES 32768          // 256 rows x 128 B
#define NSA      4                // A-ring slots
#define NSB      3                // B-ring slots
#define SMEM_CTRL 1024
#define SMEM_A0  SMEM_CTRL
#define SMEM_B0  (SMEM_CTRL + NSA * TILE_BYTES)
#define SMEM_TC  (SMEM_CTRL + (NSA + NSB) * TILE_BYTES)   // 230400
// idesc: kind::f16, dtype=F32(1<<4), atype=F16, btype=F16,
// N=256 -> (256>>3)<<17, M=128 -> (128>>4)<<24
#define GEMM_IDESC 0x8400010u

// ---- fold GEMM (W = W_org + A' @ Qt^T), K=128, tile 256x256 ----
#define FOLD_CHUNK_BYTES 32768    // 256 rows x 128 B (64 fp16 cols)
#define SMEM_FOLD (1024 + 4 * FOLD_CHUNK_BYTES)   // 132096

// ---- fallback path tiling ----
#define FB_TM    128
#define FB_TN    256
#define FB_A_BYTES (FB_TM * 128)
#define FB_B_BYTES (FB_TN * 128)
#define FB_STAGE   (FB_A_BYTES + FB_B_BYTES)
#define SMEM_FB  (4 * FB_STAGE)
#define FB_NCH   NKG              // single segment: x @ W
#define FB_TILES ((OUT_DIM / FB_TN) * (M_TOTAL / FB_TM))   // 2048

// ============================================================================
// Device scratch (static globals — no runtime allocation)
// ============================================================================
__device__ __align__(256) __half g_x1[(size_t)M_TOTAL * IN_DIM];
__device__ __align__(256) __half g_w [(size_t)OUT_DIM * IN_DIM];
__device__ __align__(256) __half g_ap16[OUT_DIM * 2 * RANK];   // A' fp16 [o,r]
__device__ __align__(256) __half g_qt16[IN_DIM * 2 * RANK];    // Qt fp16 [i,r]
__device__ __align__(256) float  g_aprime[OUT_DIM * 2 * RANK]; // fallback
__device__ int g_has_tc;

// ============================================================================
// Common PTX helpers
// ============================================================================
__device__ __forceinline__ uint32_t smem_to_u32(const void* p) {
    uint32_t a;
    asm("{ .reg .u64 t; cvta.to.shared.u64 t, %1; cvt.u32.u64 %0, t; }"
        : "=r"(a) : "l"(p));
    return a;
}

__device__ __forceinline__ void cp_async16(uint32_t dst, const void* src) {
    asm volatile("cp.async.cg.shared.global [%0], [%1], 16;"
                 :: "r"(dst), "l"(src));
}
#define CP_COMMIT() asm volatile("cp.async.commit_group;" ::: "memory")
#define CP_WAIT(n)  asm volatile("cp.async.wait_group %0;" :: "n"(n) : "memory")

__device__ __forceinline__ void ldsm_x4(uint32_t* r, uint32_t addr) {
    asm volatile("ldmatrix.sync.aligned.m8n8.x4.shared.b16 {%0,%1,%2,%3}, [%4];"
        : "=r"(r[0]), "=r"(r[1]), "=r"(r[2]), "=r"(r[3]) : "r"(addr));
}

__device__ __forceinline__ void mma16816f16(float* d, const uint32_t* a,
                                            const uint32_t* b) {
    asm volatile(
        "mma.sync.aligned.m16n8k16.row.col.f32.f16.f16.f32 "
        "{%0,%1,%2,%3}, {%4,%5,%6,%7}, {%8,%9}, {%0,%1,%2,%3};"
        : "+f"(d[0]), "+f"(d[1]), "+f"(d[2]), "+f"(d[3])
        : "r"(a[0]), "r"(a[1]), "r"(a[2]), "r"(a[3]), "r"(b[0]), "r"(b[1]));
}

#define MBARRIER_INIT(mbar, cnt) \
    asm volatile("mbarrier.init.shared.b64 [%0], %1;" \
        :: "r"((uint32_t)(mbar)), "r"((uint32_t)(cnt)) : "memory")
#define MBARRIER_EXPECT_TX(mbar, bytes) \
    asm volatile("mbarrier.arrive.expect_tx.shared.b64 _, [%0], %1;" \
        :: "r"((uint32_t)(mbar)), "r"((uint32_t)(bytes)) : "memory")
#define MBARRIER_WAIT_PARITY(mbar, parity) do { \
    uint32_t _m = (uint32_t)(mbar); uint32_t _p = (uint32_t)(parity); uint32_t _d; \
    asm volatile("{\n\t.reg .pred p;\n\t" \
        "mbarrier.try_wait.parity.acquire.cta.shared::cta.b64 p, [%1], %2;\n\t" \
        "selp.b32 %0, 1, 0, p;\n\t}" : "=r"(_d) : "r"(_m), "r"(_p) : "memory"); \
    if (!_d) { \
        asm volatile("{\n\t.reg .pred P1;\n\t" \
            "WAIT_LOOP_%=:\n\t" \
            "mbarrier.try_wait.parity.acquire.cta.shared::cta.b64 P1, [%0], %1, 0x989680;\n\t" \
            "@P1 bra.uni WAIT_DONE_%=;\n\t" \
            "bra.uni WAIT_LOOP_%=;\n\t" \
            "WAIT_DONE_%=:\n\t}" :: "r"(_m), "r"(_p) : "memory"); \
    } \
} while (0)

// TMA 2D load: global->shared::cta
__device__ __forceinline__ void tma_2d(const CUtensorMap* map, uint32_t dst,
                                       int cx, int cy, uint32_t mbar) {
    asm volatile(
        "cp.async.bulk.tensor.2d.shared::cta.global.tile.mbarrier::complete_tx::bytes "
        "[%0], [%1, {%2, %3}], [%4];"
        :: "r"(dst), "l"(map), "r"(cx), "r"(cy), "r"(mbar) : "memory");
}

// ============================================================================
// Kernel A0: A' fp32 (fallback) + fp16 (tc fold operand) + has_tc probe
// ============================================================================
__global__ void build_aprime_kernel(const float* __restrict__ p_w,
                                    const float* __restrict__ lam,
                                    const float* __restrict__ bp_w,
                                    const float* __restrict__ blam) {
    int idx = blockIdx.x * 256 + threadIdx.x;
    if (idx == 0) g_has_tc = HAS_TC;     // probe folded in (saves a launch)
    int o = idx >> 7;
    int r = idx & 127;
    float v;
    if (r < RANK) v =  p_w[o * RANK + r] * lam[r];
    else          v = -(bp_w[o * RANK + (r - RANK)] * blam[r - RANK]);
    g_aprime[idx] = v;
    g_ap16[idx]   = __float2half_rn(v);
}

// ============================================================================
// Kernel A0b: Qt[i, r] = Qcat[r, i] transposed to fp16 (tc fold operand)
// ============================================================================
__global__ __launch_bounds__(256) void transpose_q_kernel(
    const float* __restrict__ q_w, const float* __restrict__ base_q_w) {
    __shared__ float t[128][65];
    const int i0 = blockIdx.x * 64;
    const int tid = threadIdx.x;
#pragma unroll
    for (int it = 0; it < 32; ++it) {
        int idx = tid + it * 256;          // < 8192
        int r  = idx >> 6;
        int il = idx & 63;
        float v = (r < RANK) ? q_w[(size_t)r * IN_DIM + i0 + il]
                             : base_q_w[(size_t)(r - RANK) * IN_DIM + i0 + il];
        t[r][il] = v;
    }
    __syncthreads();
#pragma unroll
    for (int it = 0; it < 32; ++it) {
        int idx = tid + it * 256;
        int il = idx >> 7;
        int r  = idx & 127;
        g_qt16[(size_t)(i0 + il) * 128 + r] = __float2half_rn(t[r][il]);
    }
}

// ============================================================================
// Kernel A1 (FALLBACK ONLY): W_eff fold on the FMA pipe (256-block grid)
// ============================================================================
__global__ __launch_bounds__(256) void fold_w_kernel(
    const float* __restrict__ W_org,
    const float* __restrict__ q_w,
    const float* __restrict__ base_q_w) {
    if (g_has_tc) return;          // tensor-core fold handles it
    __shared__ float sA[16][128];
    const int o0 = blockIdx.x * 16;
    const int tid = threadIdx.x;

    for (int t = tid; t < 16 * 128; t += 256)
        sA[t >> 7][t & 127] = g_aprime[(size_t)(o0 + (t >> 7)) * 128 + (t & 127)];
    __syncthreads();

    for (int ic = 0; ic < 4; ++ic) {
        const int i = ic * 1024 + tid * 4;
        float4 acc[16];
#pragma unroll
        for (int oo = 0; oo < 16; ++oo)
            acc[oo] = *(const float4*)(W_org + (size_t)(o0 + oo) * IN_DIM + i);

#pragma unroll 4
        for (int r = 0; r < RANK; ++r) {
            float4 b = *(const float4*)(q_w + (size_t)r * IN_DIM + i);
#pragma unroll
            for (int oo = 0; oo < 16; ++oo) {
                float s = sA[oo][r];
                acc[oo].x += s * b.x; acc[oo].y += s * b.y;
                acc[oo].z += s * b.z; acc[oo].w += s * b.w;
            }
        }
#pragma unroll 4
        for (int r = 0; r < RANK; ++r) {
            float4 b = *(const float4*)(base_q_w + (size_t)r * IN_DIM + i);
#pragma unroll
            for (int oo = 0; oo < 16; ++oo) {
                float s = sA[oo][RANK + r];
                acc[oo].x += s * b.x; acc[oo].y += s * b.y;
                acc[oo].z += s * b.z; acc[oo].w += s * b.w;
            }
        }

#pragma unroll
        for (int oo = 0; oo < 16; ++oo) {
            size_t base = (size_t)(o0 + oo) * IN_DIM + i;
            __half2 h01, h23;
            h01.x = __float2half_rn(acc[oo].x);
            h01.y = __float2half_rn(acc[oo].y);
            h23.x = __float2half_rn(acc[oo].z);
            h23.y = __float2half_rn(acc[oo].w);
            __half2* pw = (__half2*)(g_w + base);
            pw[0] = h01; pw[1] = h23;
        }
    }
}

// ============================================================================
// Kernel B: convert x to fp16 (single stream)
// ============================================================================
__global__ __launch_bounds__(256) void split_x_kernel(const float4* __restrict__ x) {
    size_t i = (size_t)blockIdx.x * 256 + threadIdx.x;
    float4 v = x[i];
    __half2 h01, h23;
    h01.x = __float2half_rn(v.x);
    h01.y = __float2half_rn(v.y);
    h23.x = __float2half_rn(v.z);
    h23.y = __float2half_rn(v.w);
    ((__half2*)g_x1)[i * 2 + 0] = h01;
    ((__half2*)g_x1)[i * 2 + 1] = h23;
}

// ============================================================================
// tcgen05-only helpers
// ============================================================================
#if HAS_TC
#define TCGEN05_ALLOC(smem_addr, nCols) \
    asm volatile("tcgen05.alloc.cta_group::1.sync.aligned.shared::cta.b32 [%0], %1;" \
        :: "r"((uint32_t)(smem_addr)), "r"((uint32_t)(nCols)) : "memory")
#define TCGEN05_DEALLOC(tmem_addr, nCols) \
    asm volatile("tcgen05.dealloc.cta_group::1.sync.aligned.b32 %0, %1;" \
        :: "r"(tmem_addr), "r"((uint32_t)(nCols)))
#define TCGEN05_RELINQ() \
    asm volatile("tcgen05.relinquish_alloc_permit.cta_group::1.sync.aligned;")
#define TCGEN05_COMMIT(mbar) \
    asm volatile("tcgen05.commit.cta_group::1.mbarrier::arrive::one.shared::cluster.b64 [%0];" \
        :: "r"((uint32_t)(mbar)) : "memory")
#define TCGEN05_FENCE_AFTER() \
    asm volatile("tcgen05.fence::after_thread_sync;" ::: "memory")
#define TCGEN05_FENCE_BEFORE() \
    asm volatile("tcgen05.fence::before_thread_sync;" ::: "memory")
#define TCGEN05_WAIT_LD() \
    asm volatile("tcgen05.wait::ld.sync.aligned;" ::: "memory")
#define TCGEN05_LD_32X32B_X32(r, tmem_addr) \
    asm volatile( \
        "tcgen05.ld.sync.aligned.32x32b.x32.b32 " \
        "{%0, %1, %2, %3, %4, %5, %6, %7, " \
        " %8, %9, %10, %11, %12, %13, %14, %15, " \
        " %16, %17, %18, %19, %20, %21, %22, %23, " \
        " %24, %25, %26, %27, %28, %29, %30, %31}, [%32];" \
        : "=r"((r)[0]),  "=r"((r)[1]),  "=r"((r)[2]),  "=r"((r)[3]), \
          "=r"((r)[4]),  "=r"((r)[5]),  "=r"((r)[6]),  "=r"((r)[7]), \
          "=r"((r)[8]),  "=r"((r)[9]),  "=r"((r)[10]), "=r"((r)[11]), \
          "=r"((r)[12]), "=r"((r)[13]), "=r"((r)[14]), "=r"((r)[15]), \
          "=r"((r)[16]), "=r"((r)[17]), "=r"((r)[18]), "=r"((r)[19]), \
          "=r"((r)[20]), "=r"((r)[21]), "=r"((r)[22]), "=r"((r)[23]), \
          "=r"((r)[24]), "=r"((r)[25]), "=r"((r)[26]), "=r"((r)[27]), \
          "=r"((r)[28]), "=r"((r)[29]), "=r"((r)[30]), "=r"((r)[31]) \
        : "r"(tmem_addr))

static constexpr uint64_t SMEM_DESC_BASE_SW128 =
      (uint64_t(2)  << 61) | (uint64_t(1) << 46)
    | (uint64_t(64) << 32) | (uint64_t(1) << 16);
#define MAKE_SMEM_DESC(base_addr) \
    (SMEM_DESC_BASE_SW128 | ((uint64_t)((base_addr) >> 4) & 0x3FFF))

__device__ __forceinline__ void mma_f16_ss(uint32_t d_tmem, uint64_t a_desc,
                                           uint64_t b_desc, uint32_t idesc,
                                           uint32_t enable_d) {
    asm volatile(
        "{\n\t.reg .pred p;\n\t"
        "setp.ne.u32 p, %4, 0;\n\t"
        "tcgen05.mma.cta_group::1.kind::f16 [%0], %1, %2, %3, {%5, %5, %5, %5}, p;\n\t"
        "}"
        :: "r"(d_tmem), "l"(a_desc), "l"(b_desc), "r"(idesc),
           "r"(enable_d), "r"(0u)
        : "memory");
}
#endif // HAS_TC

// ============================================================================
// fold_tc: W = fp16( W_org + A' @ Qt^T ), K=128 (8 x K16 MMAs). cg1.
// NEW (round 13): all threads L2-prefetch the CTA's 256 KB W_org tile while
// TMA + MMA are in flight, so the epilogue's fp32 reads hit L2 (234 cyc)
// instead of DRAM (577 cyc) — removes the serial latency exposure that held
// this kernel at 35 us / 26% DRAM.
// ============================================================================
__global__ __launch_bounds__(256, 1)
void fold_tc_kernel(const float* __restrict__ W_org,
                    const __grid_constant__ CUtensorMap map_ap,
                    const __grid_constant__ CUtensorMap map_qt) {
#if HAS_TC
    extern __shared__ char smem[];
    const uint32_t smem_base = smem_to_u32(smem);
    const int tid = threadIdx.x;
    const int wid = tid >> 5;
    const int lid = tid & 31;
    const int o0 = blockIdx.y * 256;
    const int n0 = blockIdx.x * 256;

    const uint32_t MB_FULL = smem_base + 0;
    const uint32_t MB_DONE = smem_base + 8;
    const uint32_t SA0 = smem_base + 1024;
    const uint32_t SA1 = SA0 + FOLD_CHUNK_BYTES;
    const uint32_t SB0 = SA1 + FOLD_CHUNK_BYTES;
    const uint32_t SB1 = SB0 + FOLD_CHUNK_BYTES;

    if (wid == 0) {
        TCGEN05_ALLOC(smem_base + 128, 512);
        TCGEN05_RELINQ();
    }
    if (tid == 0) {
        MBARRIER_INIT(MB_FULL, 1);
        MBARRIER_INIT(MB_DONE, 1);
    }
    __syncthreads();

    uint32_t tmem;
    asm volatile("ld.shared.b32 %0, [%1];" : "=r"(tmem) : "r"(smem_base + 128));

    if (tid == 0) {
        MBARRIER_EXPECT_TX(MB_FULL, 4 * FOLD_CHUNK_BYTES);
        tma_2d(&map_ap, SA0, 0,  o0, MB_FULL);
        tma_2d(&map_ap, SA1, 64, o0, MB_FULL);
        tma_2d(&map_qt, SB0, 0,  n0, MB_FULL);
        tma_2d(&map_qt, SB1, 64, n0, MB_FULL);
    }

    // L2-prefetch this CTA's W_org tile (256 rows x 1 KB): thread t covers row
    // o0+t (8 x 128 B lines). Overlaps TMA + MMA latency.
    {
        const float* wp = W_org + (size_t)(o0 + tid) * IN_DIM + n0;
#pragma unroll
        for (int j = 0; j < 8; ++j)
            asm volatile("prefetch.global.L2 [%0];" :: "l"(wp + j * 32));
    }

    if (tid == 0) {
        MBARRIER_WAIT_PARITY(MB_FULL, 0);
        const uint64_t a00 = MAKE_SMEM_DESC(SA0);
        const uint64_t a01 = MAKE_SMEM_DESC(SA0 + 16384);
        const uint64_t a10 = MAKE_SMEM_DESC(SA1);
        const uint64_t a11 = MAKE_SMEM_DESC(SA1 + 16384);
        const uint64_t b0  = MAKE_SMEM_DESC(SB0);
        const uint64_t b1  = MAKE_SMEM_DESC(SB1);
#pragma unroll
        for (int k = 0; k < 4; ++k) {
            uint32_t en = (k > 0) ? 1u : 0u;
            mma_f16_ss(tmem,       a00 + k * 2, b0 + k * 2, GEMM_IDESC, en);
            mma_f16_ss(tmem + 256, a01 + k * 2, b0 + k * 2, GEMM_IDESC, en);
        }
#pragma unroll
        for (int k = 0; k < 4; ++k) {
            mma_f16_ss(tmem,       a10 + k * 2, b1 + k * 2, GEMM_IDESC, 1u);
            mma_f16_ss(tmem + 256, a11 + k * 2, b1 + k * 2, GEMM_IDESC, 1u);
        }
        TCGEN05_COMMIT(MB_DONE);
    }

    MBARRIER_WAIT_PARITY(MB_DONE, 0);
    TCGEN05_FENCE_AFTER();
    {
        const int half = wid >> 2;
        const int sub  = wid & 3;
        const uint32_t lane_off = ((uint32_t)sub) << 21;
        const int o = o0 + half * 128 + sub * 32 + lid;
        const float* wsrc = W_org + (size_t)o * IN_DIM + n0;
        __half* wdst = g_w + (size_t)o * IN_DIM + n0;
#pragma unroll
        for (int cc = 0; cc < 8; ++cc) {
            uint32_t r[32];
            TCGEN05_LD_32X32B_X32(
                r, tmem + lane_off + (uint32_t)(half * 256 + cc * 32));
            TCGEN05_WAIT_LD();
            __half2 hv[16];
#pragma unroll
            for (int q = 0; q < 8; ++q) {
                float4 w = *(const float4*)(wsrc + cc * 32 + q * 4);
                hv[2 * q].x     = __float2half_rn(__uint_as_float(r[4 * q + 0]) + w.x);
                hv[2 * q].y     = __float2half_rn(__uint_as_float(r[4 * q + 1]) + w.y);
                hv[2 * q + 1].x = __float2half_rn(__uint_as_float(r[4 * q + 2]) + w.z);
                hv[2 * q + 1].y = __float2half_rn(__uint_as_float(r[4 * q + 3]) + w.w);
            }
            uint4* dst = (uint4*)(wdst + cc * 32);
            const uint4* src = (const uint4*)hv;
#pragma unroll
            for (int q = 0; q < 4; ++q) dst[q] = src[q];
        }
        TCGEN05_FENCE_BEFORE();
    }
    __syncthreads();
    if (wid == 0) TCGEN05_DEALLOC(tmem, 512);
#else
    (void)W_org; (void)map_ap; (void)map_qt;
#endif
}

// ============================================================================
// Main GEMM (tcgen05, cg1): 256x256 tile, single fp16 product, TMA pipeline.
// Byte-identical logic to the 486us winner (at its LTS-cap floor).
// ============================================================================
__global__ __launch_bounds__(256, 1)
void gemm_tc_kernel(float* __restrict__ out,
                    const __grid_constant__ CUtensorMap mx1,
                    const __grid_constant__ CUtensorMap mw) {
#if HAS_TC
    extern __shared__ char smem[];
    const uint32_t smem_base = smem_to_u32(smem);
    const int tid = threadIdx.x;
    const int wid = tid >> 5;
    const int lid = tid & 31;
    const int m0 = blockIdx.y * TILE_M;
    const int n0 = blockIdx.x * TILE_N;

    const uint32_t MB_FULLA  = smem_base + 0;
    const uint32_t MB_FULLB  = smem_base + 32;
    const uint32_t MB_EMPTYA = smem_base + 56;
    const uint32_t MB_EMPTYB = smem_base + 88;
    const uint32_t MB_DONE   = smem_base + 112;

    if (wid == 0) {
        TCGEN05_ALLOC(smem_base + 128, 512);
        TCGEN05_RELINQ();
    }
    if (tid == 0) {
#pragma unroll
        for (int s = 0; s < NSA; ++s) { MBARRIER_INIT(MB_FULLA + 8 * s, 1);
                                        MBARRIER_INIT(MB_EMPTYA + 8 * s, 1); }
#pragma unroll
        for (int s = 0; s < NSB; ++s) { MBARRIER_INIT(MB_FULLB + 8 * s, 1);
                                        MBARRIER_INIT(MB_EMPTYB + 8 * s, 1); }
        MBARRIER_INIT(MB_DONE, 1);
    }
    __syncthreads();

    uint32_t tmem;
    asm volatile("ld.shared.b32 %0, [%1];" : "=r"(tmem) : "r"(smem_base + 128));

    if (tid == 32) {
        for (int g = 0; g < NKG; ++g) {
            const int cx = g * 64;
            {
                const int s = g & (NSA - 1);
                MBARRIER_WAIT_PARITY(MB_EMPTYA + 8 * s, ((g >> 2) & 1) ^ 1);
                MBARRIER_EXPECT_TX(MB_FULLA + 8 * s, TILE_BYTES);
                tma_2d(&mx1, smem_base + SMEM_A0 + s * TILE_BYTES,
                       cx, m0, MB_FULLA + 8 * s);
            }
            {
                const int s = g % NSB;
                MBARRIER_WAIT_PARITY(MB_EMPTYB + 8 * s, ((g / NSB) & 1) ^ 1);
                MBARRIER_EXPECT_TX(MB_FULLB + 8 * s, TILE_BYTES);
                tma_2d(&mw, smem_base + SMEM_B0 + s * TILE_BYTES,
                       cx, n0, MB_FULLB + 8 * s);
            }
        }
    } else if (tid == 0) {
        for (int g = 0; g < NKG; ++g) {
            const int sa = g & (NSA - 1);
            const int sb = g % NSB;

            const uint32_t saddr = smem_base + SMEM_A0 + sa * TILE_BYTES;
            const uint64_t a0 = MAKE_SMEM_DESC(saddr);
            const uint64_t a1 = MAKE_SMEM_DESC(saddr + 16384);
            const uint64_t bd = MAKE_SMEM_DESC(smem_base + SMEM_B0 + sb * TILE_BYTES);

            MBARRIER_WAIT_PARITY(MB_FULLA + 8 * sa, (g >> 2) & 1);
            MBARRIER_WAIT_PARITY(MB_FULLB + 8 * sb, (g / NSB) & 1);
#pragma unroll
            for (int k = 0; k < 4; ++k) {
                uint32_t en = (g > 0 || k > 0) ? 1u : 0u;
                mma_f16_ss(tmem,       a0 + k * 2, bd + k * 2, GEMM_IDESC, en);
                mma_f16_ss(tmem + 256, a1 + k * 2, bd + k * 2, GEMM_IDESC, en);
            }
            TCGEN05_COMMIT(MB_EMPTYA + 8 * sa);
            TCGEN05_COMMIT(MB_EMPTYB + 8 * sb);
        }
        TCGEN05_COMMIT(MB_DONE);
    }

    MBARRIER_WAIT_PARITY(MB_DONE, 0);
    TCGEN05_FENCE_AFTER();
    {
        const int half = wid >> 2;
        const int sub  = wid & 3;
        const uint32_t lane_off = ((uint32_t)sub) << 21;
        const int m = m0 + half * 128 + sub * 32 + lid;
        float* orow = out + (size_t)m * OUT_DIM + n0;
#pragma unroll
        for (int cc = 0; cc < 8; ++cc) {
            uint32_t r[32];
            TCGEN05_LD_32X32B_X32(
                r, tmem + lane_off + (uint32_t)(half * 256 + cc * 32));
            TCGEN05_WAIT_LD();
            float* dst = orow + cc * 32;
#pragma unroll
            for (int q = 0; q < 8; ++q) {
                float4 v;
                v.x = __uint_as_float(r[4 * q + 0]);
                v.y = __uint_as_float(r[4 * q + 1]);
                v.z = __uint_as_float(r[4 * q + 2]);
                v.w = __uint_as_float(r[4 * q + 3]);
                ((float4*)dst)[q] = v;
            }
        }
        TCGEN05_FENCE_BEFORE();
    }

    __syncthreads();
    if (wid == 0) TCGEN05_DEALLOC(tmem, 512);
#else
    (void)out; (void)mx1; (void)mw;
#endif
}

// ============================================================================
// GEMM (mma.sync fallback) — grid-stride over 2048 tiles; early-exits when
// the tcgen05 path is live.
// ============================================================================
__global__ __launch_bounds__(512, 1)
void gemm_fb_kernel(float* __restrict__ out) {
    if (g_has_tc) return;

    extern __shared__ char smem[];
    const uint32_t smem_base = smem_to_u32(smem);
    const int tid = threadIdx.x;
    const int wid = tid >> 5;
    const int lid = tid & 31;
    const int wm = wid & 3;
    const int wn = wid >> 2;

    const int ar  = wm * 32 + (lid & 15);
    const int ca  = lid >> 4;
    const int axr = ar & 7;
    const int bn  = wn * 64 + (lid & 7) + ((lid >> 4) << 3);
    const int kb  = (lid >> 3) & 1;
    const int bxr = bn & 7;

    for (int tile = blockIdx.x; tile < FB_TILES; tile += gridDim.x) {
        const int m0 = (tile >> 4) * FB_TM;
        const int n0 = (tile & 15) * FB_TN;

        float acc[2][8][4];
#pragma unroll
        for (int i = 0; i < 2; ++i)
#pragma unroll
            for (int j = 0; j < 8; ++j)
#pragma unroll
                for (int k = 0; k < 4; ++k) acc[i][j][k] = 0.f;

        auto load_chunk = [&](int c) {
            const int st = c & 3;
            const int k0 = c << 6;
            const __half* Ab = g_x1 + (size_t)m0 * IN_DIM + k0;
            const __half* Bb = g_w  + (size_t)n0 * IN_DIM + k0;
            const uint32_t sa = smem_base + st * FB_STAGE;
            const uint32_t sb = sa + FB_A_BYTES;
#pragma unroll
            for (int it = 0; it < 2; ++it) {
                int i = tid + it * 512;
                int row = i >> 3, j = i & 7;
                uint32_t dst = sa + row * 128 + ((uint32_t)(j ^ (row & 7)) << 4);
                cp_async16(dst, Ab + (size_t)row * IN_DIM + j * 8);
            }
#pragma unroll
            for (int it = 0; it < 4; ++it) {
                int i = tid + it * 512;
                int row = i >> 3, j = i & 7;
                uint32_t dst = sb + row * 128 + ((uint32_t)(j ^ (row & 7)) << 4);
                cp_async16(dst, Bb + (size_t)row * IN_DIM + j * 8);
            }
            CP_COMMIT();
        };

        load_chunk(0);
        load_chunk(1);
        load_chunk(2);

        for (int c = 0; c < FB_NCH; ++c) {
            const int rem = FB_NCH - 1 - c;
            if (rem >= 2)      CP_WAIT(2);
            else if (rem == 1) CP_WAIT(1);
            else               CP_WAIT(0);
            __syncthreads();
            if (c + 3 < FB_NCH) load_chunk(c + 3);

            const uint32_t sa = smem_base + (c & 3) * FB_STAGE;
            const uint32_t sb = sa + FB_A_BYTES;

#pragma unroll
            for (int s = 0; s < 4; ++s) {
                uint32_t a[2][4];
#pragma unroll
                for (int mb = 0; mb < 2; ++mb) {
                    uint32_t addr = sa + (ar + mb * 16) * 128
                                  + ((uint32_t)(((s << 1) + ca) ^ axr) << 4);
                    ldsm_x4(a[mb], addr);
                }
#pragma unroll
                for (int nb = 0; nb < 4; ++nb) {
                    uint32_t b[4];
                    uint32_t addr = sb + (bn + nb * 16) * 128
                                  + ((uint32_t)(((s << 1) + kb) ^ bxr) << 4);
                    ldsm_x4(b, addr);
#pragma unroll
                    for (int mb = 0; mb < 2; ++mb) {
                        mma16816f16(acc[mb][nb * 2 + 0], a[mb], b + 0);
                        mma16816f16(acc[mb][nb * 2 + 1], a[mb], b + 2);
                    }
                }
            }
        }
        __syncthreads();   // smem reuse safety before next tile's loads

#pragma unroll
        for (int mb = 0; mb < 2; ++mb) {
            const int r0 = m0 + wm * 32 + mb * 16 + (lid >> 2);
#pragma unroll
            for (int nb8 = 0; nb8 < 8; ++nb8) {
                const int col = n0 + wn * 64 + nb8 * 8 + (lid & 3) * 2;
                float2 v0; v0.x = acc[mb][nb8][0]; v0.y = acc[mb][nb8][1];
                float2 v1; v1.x = acc[mb][nb8][2]; v1.y = acc[mb][nb8][3];
                *(float2*)(out + (size_t)r0 * OUT_DIM + col)       = v0;
                *(float2*)(out + (size_t)(r0 + 8) * OUT_DIM + col) = v1;
            }
        }
    }
}

// ============================================================================
// Host: tensor-map construction via driver entry point (no -lcuda link)
// ============================================================================
typedef CUresult (*PFN_tmeTiled)(
    CUtensorMap*, CUtensorMapDataType, unsigned int, void*,
    const unsigned long long*, const unsigned long long*,
    const unsigned int*, const unsigned int*,
    CUtensorMapInterleave, CUtensorMapSwizzle,
    CUtensorMapL2promotion, CUtensorMapFloatOOBfill);

static void make_map(PFN_tmeTiled enc, CUtensorMap* m, void* base,
                     unsigned long long cols, unsigned long long rows) {
    unsigned long long dims[2]    = {cols, rows};
    unsigned long long strides[1] = {cols * sizeof(__half)};
    unsigned int box[2]  = {64, 256};
    unsigned int es[2]   = {1, 1};
    enc(m, CU_TENSOR_MAP_DATA_TYPE_FLOAT16, 2, base, dims, strides, box, es,
        CU_TENSOR_MAP_INTERLEAVE_NONE, CU_TENSOR_MAP_SWIZZLE_128B,
        CU_TENSOR_MAP_L2_PROMOTION_L2_128B, CU_TENSOR_MAP_FLOAT_OOB_FILL_NONE);
}

extern "C" void kernel_launch(void* const* d_in, const int* in_sizes, int n_in,
                              void* d_out, int out_size) {
    (void)in_sizes; (void)n_in; (void)out_size;
    const float* x      = (const float*)d_in[0];
    const float* W_org  = (const float*)d_in[1];
    const float* q_w    = (const float*)d_in[2];
    const float* p_w    = (const float*)d_in[3];
    const float* lam    = (const float*)d_in[4];
    const float* bq_w   = (const float*)d_in[5];
    const float* bp_w   = (const float*)d_in[6];
    const float* blam   = (const float*)d_in[7];
    float* out = (float*)d_out;

    cudaFuncSetAttribute(gemm_tc_kernel,
                         cudaFuncAttributeMaxDynamicSharedMemorySize, SMEM_TC);
    cudaFuncSetAttribute(fold_tc_kernel,
                         cudaFuncAttributeMaxDynamicSharedMemorySize, SMEM_FOLD);
    cudaFuncSetAttribute(gemm_fb_kernel,
                         cudaFuncAttributeMaxDynamicSharedMemorySize, SMEM_FB);

    void* fn = nullptr;
    cudaDriverEntryPointQueryResult qst;
    cudaGetDriverEntryPoint("cuTensorMapEncodeTiled", &fn,
                            cudaEnableDefault, &qst);
    PFN_tmeTiled enc = (PFN_tmeTiled)fn;

    void *p_x1, *p_w_, *p_ap, *p_qt;
    cudaGetSymbolAddress(&p_x1, g_x1);
    cudaGetSymbolAddress(&p_w_, g_w);
    cudaGetSymbolAddress(&p_ap, g_ap16);
    cudaGetSymbolAddress(&p_qt, g_qt16);

    CUtensorMap mx1{}, mw{}, map_ap{}, map_qt{};
    make_map(enc, &mx1, p_x1, IN_DIM, M_TOTAL);
    make_map(enc, &mw,  p_w_, IN_DIM, OUT_DIM);
    make_map(enc, &map_ap, p_ap, 128, OUT_DIM);
    make_map(enc, &map_qt, p_qt, 128, IN_DIM);

    build_aprime_kernel<<<(OUT_DIM * 2 * RANK) / 256, 256>>>(p_w, lam, bp_w, blam);
    transpose_q_kernel<<<IN_DIM / 64, 256>>>(q_w, bq_w);
    fold_w_kernel<<<OUT_DIM / 16, 256>>>(W_org, q_w, bq_w);
    fold_tc_kernel<<<dim3(IN_DIM / 256, OUT_DIM / 256), 256, SMEM_FOLD>>>(
        W_org, map_ap, map_qt);
    split_x_kernel<<<(int)(((size_t)M_TOTAL * IN_DIM / 4) / 256), 256>>>(
        (const float4*)x);

    gemm_tc_kernel<<<dim3(OUT_DIM / TILE_N, M_TOTAL / TILE_M), 256, SMEM_TC>>>(
        out, mx1, mw);
    gemm_fb_kernel<<<512, 512, SMEM_FB>>>(out);
}

// round 14
// speedup vs baseline: 1.0157x; 1.0157x over previous
#include <cuda_runtime.h>
#include <cuda.h>
#include <cuda_fp16.h>
#include <cstdint>

// ============================================================================
// Feature gate: tcgen05 exists only on the sm_103a pass (proven live by
// rounds 3-13). mma.sync / FMA fallbacks retained, gated by g_has_tc.
// ============================================================================
#if defined(__CUDA_ARCH__) && defined(__CUDA_ARCH_FEAT_SM103_ALL)
#define HAS_TC 1
#else
#define HAS_TC 0
#endif

// ============================================================================
// Problem constants
// ============================================================================
#define IN_DIM   4096
#define OUT_DIM  4096
#define RANK     64
#define M_TOTAL  16384            // 4 * 4096 rows of x

#define NKG      64               // K groups of 64 fp16 columns

// ---- tcgen05 main GEMM: 256x256 CTA tile, single fp16 product ----
#define TILE_M   256
#define TILE_N   256
#define TILE_BYTES 32768          // 256 rows x 128 B
#define NSA      4                // A-ring slots
#define NSB      3                // B-ring slots
#define SMEM_CTRL 1024
#define SMEM_A0  SMEM_CTRL
#define SMEM_B0  (SMEM_CTRL + NSA * TILE_BYTES)
#define SMEM_TC  (SMEM_CTRL + (NSA + NSB) * TILE_BYTES)   // 230400
// idesc: kind::f16, dtype=F32(1<<4), atype=F16, btype=F16,
// N=256 -> (256>>3)<<17, M=128 -> (128>>4)<<24
#define GEMM_IDESC 0x8400010u

// ---- fold GEMM (W = W_org + A' @ Qt^T), K=128, tile 128(o) x 256(n) ----
// 2 CTAs/SM (97 KB smem) so TMA/MMA latency of one CTA overlaps the other's
// epilogue — round-13 showed the 256x256 single-CTA version was latency-bound.
#define FOLD_A_CHUNK 16384        // 128 rows x 128 B
#define FOLD_B_CHUNK 32768        // 256 rows x 128 B
#define SMEM_FOLD (1024 + 2 * FOLD_A_CHUNK + 2 * FOLD_B_CHUNK)   // 99328

// ---- fallback path tiling ----
#define FB_TM    128
#define FB_TN    256
#define FB_A_BYTES (FB_TM * 128)
#define FB_B_BYTES (FB_TN * 128)
#define FB_STAGE   (FB_A_BYTES + FB_B_BYTES)
#define SMEM_FB  (4 * FB_STAGE)
#define FB_NCH   NKG              // single segment: x @ W
#define FB_TILES ((OUT_DIM / FB_TN) * (M_TOTAL / FB_TM))   // 2048

// ============================================================================
// Device scratch (static globals — no runtime allocation)
// ============================================================================
__device__ __align__(256) __half g_x1[(size_t)M_TOTAL * IN_DIM];
__device__ __align__(256) __half g_w [(size_t)OUT_DIM * IN_DIM];
__device__ __align__(256) __half g_ap16[OUT_DIM * 2 * RANK];   // A' fp16 [o,r]
__device__ __align__(256) __half g_qt16[IN_DIM * 2 * RANK];    // Qt fp16 [i,r]
__device__ __align__(256) float  g_aprime[OUT_DIM * 2 * RANK]; // fallback
__device__ int g_has_tc;

// ============================================================================
// Common PTX helpers
// ============================================================================
__device__ __forceinline__ uint32_t smem_to_u32(const void* p) {
    uint32_t a;
    asm("{ .reg .u64 t; cvta.to.shared.u64 t, %1; cvt.u32.u64 %0, t; }"
        : "=r"(a) : "l"(p));
    return a;
}

__device__ __forceinline__ void cp_async16(uint32_t dst, const void* src) {
    asm volatile("cp.async.cg.shared.global [%0], [%1], 16;"
                 :: "r"(dst), "l"(src));
}
#define CP_COMMIT() asm volatile("cp.async.commit_group;" ::: "memory")
#define CP_WAIT(n)  asm volatile("cp.async.wait_group %0;" :: "n"(n) : "memory")

__device__ __forceinline__ void ldsm_x4(uint32_t* r, uint32_t addr) {
    asm volatile("ldmatrix.sync.aligned.m8n8.x4.shared.b16 {%0,%1,%2,%3}, [%4];"
        : "=r"(r[0]), "=r"(r[1]), "=r"(r[2]), "=r"(r[3]) : "r"(addr));
}

__device__ __forceinline__ void mma16816f16(float* d, const uint32_t* a,
                                            const uint32_t* b) {
    asm volatile(
        "mma.sync.aligned.m16n8k16.row.col.f32.f16.f16.f32 "
        "{%0,%1,%2,%3}, {%4,%5,%6,%7}, {%8,%9}, {%0,%1,%2,%3};"
        : "+f"(d[0]), "+f"(d[1]), "+f"(d[2]), "+f"(d[3])
        : "r"(a[0]), "r"(a[1]), "r"(a[2]), "r"(a[3]), "r"(b[0]), "r"(b[1]));
}

#define MBARRIER_INIT(mbar, cnt) \
    asm volatile("mbarrier.init.shared.b64 [%0], %1;" \
        :: "r"((uint32_t)(mbar)), "r"((uint32_t)(cnt)) : "memory")
#define MBARRIER_EXPECT_TX(mbar, bytes) \
    asm volatile("mbarrier.arrive.expect_tx.shared.b64 _, [%0], %1;" \
        :: "r"((uint32_t)(mbar)), "r"((uint32_t)(bytes)) : "memory")
#define MBARRIER_WAIT_PARITY(mbar, parity) do { \
    uint32_t _m = (uint32_t)(mbar); uint32_t _p = (uint32_t)(parity); uint32_t _d; \
    asm volatile("{\n\t.reg .pred p;\n\t" \
        "mbarrier.try_wait.parity.acquire.cta.shared::cta.b64 p, [%1], %2;\n\t" \
        "selp.b32 %0, 1, 0, p;\n\t}" : "=r"(_d) : "r"(_m), "r"(_p) : "memory"); \
    if (!_d) { \
        asm volatile("{\n\t.reg .pred P1;\n\t" \
            "WAIT_LOOP_%=:\n\t" \
            "mbarrier.try_wait.parity.acquire.cta.shared::cta.b64 P1, [%0], %1, 0x989680;\n\t" \
            "@P1 bra.uni WAIT_DONE_%=;\n\t" \
            "bra.uni WAIT_LOOP_%=;\n\t" \
            "WAIT_DONE_%=:\n\t}" :: "r"(_m), "r"(_p) : "memory"); \
    } \
} while (0)

// TMA 2D load: global->shared::cta
__device__ __forceinline__ void tma_2d(const CUtensorMap* map, uint32_t dst,
                                       int cx, int cy, uint32_t mbar) {
    asm volatile(
        "cp.async.bulk.tensor.2d.shared::cta.global.tile.mbarrier::complete_tx::bytes "
        "[%0], [%1, {%2, %3}], [%4];"
        :: "r"(dst), "l"(map), "r"(cx), "r"(cy), "r"(mbar) : "memory");
}

// ============================================================================
// Kernel A0: A' fp32 (fallback) + fp16 (tc fold operand) + has_tc probe
// ============================================================================
__global__ void build_aprime_kernel(const float* __restrict__ p_w,
                                    const float* __restrict__ lam,
                                    const float* __restrict__ bp_w,
                                    const float* __restrict__ blam) {
    int idx = blockIdx.x * 256 + threadIdx.x;
    if (idx == 0) g_has_tc = HAS_TC;
    int o = idx >> 7;
    int r = idx & 127;
    float v;
    if (r < RANK) v =  p_w[o * RANK + r] * lam[r];
    else          v = -(bp_w[o * RANK + (r - RANK)] * blam[r - RANK]);
    g_aprime[idx] = v;
    g_ap16[idx]   = __float2half_rn(v);
}

// ============================================================================
// Kernel A0b: Qt[i, r] = Qcat[r, i] transposed to fp16 (tc fold operand)
// ============================================================================
__global__ __launch_bounds__(256) void transpose_q_kernel(
    const float* __restrict__ q_w, const float* __restrict__ base_q_w) {
    __shared__ float t[128][65];
    const int i0 = blockIdx.x * 64;
    const int tid = threadIdx.x;
#pragma unroll
    for (int it = 0; it < 32; ++it) {
        int idx = tid + it * 256;
        int r  = idx >> 6;
        int il = idx & 63;
        float v = (r < RANK) ? q_w[(size_t)r * IN_DIM + i0 + il]
                             : base_q_w[(size_t)(r - RANK) * IN_DIM + i0 + il];
        t[r][il] = v;
    }
    __syncthreads();
#pragma unroll
    for (int it = 0; it < 32; ++it) {
        int idx = tid + it * 256;
        int il = idx >> 7;
        int r  = idx & 127;
        g_qt16[(size_t)(i0 + il) * 128 + r] = __float2half_rn(t[r][il]);
    }
}

// ============================================================================
// Kernel A1 (FALLBACK ONLY): W_eff fold on the FMA pipe (256-block grid)
// ============================================================================
__global__ __launch_bounds__(256) void fold_w_kernel(
    const float* __restrict__ W_org,
    const float* __restrict__ q_w,
    const float* __restrict__ base_q_w) {
    if (g_has_tc) return;
    __shared__ float sA[16][128];
    const int o0 = blockIdx.x * 16;
    const int tid = threadIdx.x;

    for (int t = tid; t < 16 * 128; t += 256)
        sA[t >> 7][t & 127] = g_aprime[(size_t)(o0 + (t >> 7)) * 128 + (t & 127)];
    __syncthreads();

    for (int ic = 0; ic < 4; ++ic) {
        const int i = ic * 1024 + tid * 4;
        float4 acc[16];
#pragma unroll
        for (int oo = 0; oo < 16; ++oo)
            acc[oo] = *(const float4*)(W_org + (size_t)(o0 + oo) * IN_DIM + i);

#pragma unroll 4
        for (int r = 0; r < RANK; ++r) {
            float4 b = *(const float4*)(q_w + (size_t)r * IN_DIM + i);
#pragma unroll
            for (int oo = 0; oo < 16; ++oo) {
                float s = sA[oo][r];
                acc[oo].x += s * b.x; acc[oo].y += s * b.y;
                acc[oo].z += s * b.z; acc[oo].w += s * b.w;
            }
        }
#pragma unroll 4
        for (int r = 0; r < RANK; ++r) {
            float4 b = *(const float4*)(base_q_w + (size_t)r * IN_DIM + i);
#pragma unroll
            for (int oo = 0; oo < 16; ++oo) {
                float s = sA[oo][RANK + r];
                acc[oo].x += s * b.x; acc[oo].y += s * b.y;
                acc[oo].z += s * b.z; acc[oo].w += s * b.w;
            }
        }

#pragma unroll
        for (int oo = 0; oo < 16; ++oo) {
            size_t base = (size_t)(o0 + oo) * IN_DIM + i;
            __half2 h01, h23;
            h01.x = __float2half_rn(acc[oo].x);
            h01.y = __float2half_rn(acc[oo].y);
            h23.x = __float2half_rn(acc[oo].z);
            h23.y = __float2half_rn(acc[oo].w);
            __half2* pw = (__half2*)(g_w + base);
            pw[0] = h01; pw[1] = h23;
        }
    }
}

// ============================================================================
// Kernel B: convert x to fp16 (single stream)
// ============================================================================
__global__ __launch_bounds__(256) void split_x_kernel(const float4* __restrict__ x) {
    size_t i = (size_t)blockIdx.x * 256 + threadIdx.x;
    float4 v = x[i];
    __half2 h01, h23;
    h01.x = __float2half_rn(v.x);
    h01.y = __float2half_rn(v.y);
    h23.x = __float2half_rn(v.z);
    h23.y = __float2half_rn(v.w);
    ((__half2*)g_x1)[i * 2 + 0] = h01;
    ((__half2*)g_x1)[i * 2 + 1] = h23;
}

// ============================================================================
// tcgen05-only helpers
// ============================================================================
#if HAS_TC
#define TCGEN05_ALLOC(smem_addr, nCols) \
    asm volatile("tcgen05.alloc.cta_group::1.sync.aligned.shared::cta.b32 [%0], %1;" \
        :: "r"((uint32_t)(smem_addr)), "r"((uint32_t)(nCols)) : "memory")
#define TCGEN05_DEALLOC(tmem_addr, nCols) \
    asm volatile("tcgen05.dealloc.cta_group::1.sync.aligned.b32 %0, %1;" \
        :: "r"(tmem_addr), "r"((uint32_t)(nCols)))
#define TCGEN05_RELINQ() \
    asm volatile("tcgen05.relinquish_alloc_permit.cta_group::1.sync.aligned;")
#define TCGEN05_COMMIT(mbar) \
    asm volatile("tcgen05.commit.cta_group::1.mbarrier::arrive::one.shared::cluster.b64 [%0];" \
        :: "r"((uint32_t)(mbar)) : "memory")
#define TCGEN05_FENCE_AFTER() \
    asm volatile("tcgen05.fence::after_thread_sync;" ::: "memory")
#define TCGEN05_FENCE_BEFORE() \
    asm volatile("tcgen05.fence::before_thread_sync;" ::: "memory")
#define TCGEN05_WAIT_LD() \
    asm volatile("tcgen05.wait::ld.sync.aligned;" ::: "memory")
#define TCGEN05_LD_32X32B_X32(r, tmem_addr) \
    asm volatile( \
        "tcgen05.ld.sync.aligned.32x32b.x32.b32 " \
        "{%0, %1, %2, %3, %4, %5, %6, %7, " \
        " %8, %9, %10, %11, %12, %13, %14, %15, " \
        " %16, %17, %18, %19, %20, %21, %22, %23, " \
        " %24, %25, %26, %27, %28, %29, %30, %31}, [%32];" \
        : "=r"((r)[0]),  "=r"((r)[1]),  "=r"((r)[2]),  "=r"((r)[3]), \
          "=r"((r)[4]),  "=r"((r)[5]),  "=r"((r)[6]),  "=r"((r)[7]), \
          "=r"((r)[8]),  "=r"((r)[9]),  "=r"((r)[10]), "=r"((r)[11]), \
          "=r"((r)[12]), "=r"((r)[13]), "=r"((r)[14]), "=r"((r)[15]), \
          "=r"((r)[16]), "=r"((r)[17]), "=r"((r)[18]), "=r"((r)[19]), \
          "=r"((r)[20]), "=r"((r)[21]), "=r"((r)[22]), "=r"((r)[23]), \
          "=r"((r)[24]), "=r"((r)[25]), "=r"((r)[26]), "=r"((r)[27]), \
          "=r"((r)[28]), "=r"((r)[29]), "=r"((r)[30]), "=r"((r)[31]) \
        : "r"(tmem_addr))

static constexpr uint64_t SMEM_DESC_BASE_SW128 =
      (uint64_t(2)  << 61) | (uint64_t(1) << 46)
    | (uint64_t(64) << 32) | (uint64_t(1) << 16);
#define MAKE_SMEM_DESC(base_addr) \
    (SMEM_DESC_BASE_SW128 | ((uint64_t)((base_addr) >> 4) & 0x3FFF))

__device__ __forceinline__ void mma_f16_ss(uint32_t d_tmem, uint64_t a_desc,
                                           uint64_t b_desc, uint32_t idesc,
                                           uint32_t enable_d) {
    asm volatile(
        "{\n\t.reg .pred p;\n\t"
        "setp.ne.u32 p, %4, 0;\n\t"
        "tcgen05.mma.cta_group::1.kind::f16 [%0], %1, %2, %3, {%5, %5, %5, %5}, p;\n\t"
        "}"
        :: "r"(d_tmem), "l"(a_desc), "l"(b_desc), "r"(idesc),
           "r"(enable_d), "r"(0u)
        : "memory");
}
#endif // HAS_TC

// ============================================================================
// fold_tc: W = fp16( W_org + A' @ Qt^T ), K=128 (8 x K16 MMAs). cg1.
// Round 14: tile 128(o) x 256(n), 97 KB smem -> 2 CTAs/SM so one CTA's
// epilogue overlaps the other's TMA+MMA chain (round-13 showed the 256x256
// 1-CTA/SM version was serial-latency-bound at 37 us).
// ============================================================================
__global__ __launch_bounds__(256, 2)
void fold_tc_kernel(const float* __restrict__ W_org,
                    const __grid_constant__ CUtensorMap map_ap,
                    const __grid_constant__ CUtensorMap map_qt) {
#if HAS_TC
    extern __shared__ char smem[];
    const uint32_t smem_base = smem_to_u32(smem);
    const int tid = threadIdx.x;
    const int wid = tid >> 5;
    const int lid = tid & 31;
    const int o0 = blockIdx.y * 128;
    const int n0 = blockIdx.x * 256;

    const uint32_t MB_FULL = smem_base + 0;
    const uint32_t MB_DONE = smem_base + 8;
    const uint32_t SA0 = smem_base + 1024;
    const uint32_t SA1 = SA0 + FOLD_A_CHUNK;
    const uint32_t SB0 = SA1 + FOLD_A_CHUNK;
    const uint32_t SB1 = SB0 + FOLD_B_CHUNK;

    if (wid == 0) {
        TCGEN05_ALLOC(smem_base + 128, 256);
        TCGEN05_RELINQ();
    }
    if (tid == 0) {
        MBARRIER_INIT(MB_FULL, 1);
        MBARRIER_INIT(MB_DONE, 1);
    }
    __syncthreads();

    uint32_t tmem;
    asm volatile("ld.shared.b32 %0, [%1];" : "=r"(tmem) : "r"(smem_base + 128));

    if (tid == 0) {
        MBARRIER_EXPECT_TX(MB_FULL, 2 * FOLD_A_CHUNK + 2 * FOLD_B_CHUNK);
        tma_2d(&map_ap, SA0, 0,  o0, MB_FULL);     // A' rows o0..o0+127, r 0..63
        tma_2d(&map_ap, SA1, 64, o0, MB_FULL);     // r 64..127
        tma_2d(&map_qt, SB0, 0,  n0, MB_FULL);     // Qt rows n0..n0+255, r 0..63
        tma_2d(&map_qt, SB1, 64, n0, MB_FULL);     // r 64..127

        MBARRIER_WAIT_PARITY(MB_FULL, 0);
        const uint64_t a0 = MAKE_SMEM_DESC(SA0);
        const uint64_t a1 = MAKE_SMEM_DESC(SA1);
        const uint64_t b0 = MAKE_SMEM_DESC(SB0);
        const uint64_t b1 = MAKE_SMEM_DESC(SB1);
#pragma unroll
        for (int k = 0; k < 4; ++k) {
            uint32_t en = (k > 0) ? 1u : 0u;
            mma_f16_ss(tmem, a0 + k * 2, b0 + k * 2, GEMM_IDESC, en);
        }
#pragma unroll
        for (int k = 0; k < 4; ++k) {
            mma_f16_ss(tmem, a1 + k * 2, b1 + k * 2, GEMM_IDESC, 1u);
        }
        TCGEN05_COMMIT(MB_DONE);
    }

    MBARRIER_WAIT_PARITY(MB_DONE, 0);
    TCGEN05_FENCE_AFTER();
    {
        const int sub  = wid & 3;                // TMEM subpartition (rows)
        const int half = wid >> 2;               // column half (0/1)
        const uint32_t lane_off = ((uint32_t)sub) << 21;
        const int o = o0 + sub * 32 + lid;
        const float* wsrc = W_org + (size_t)o * IN_DIM + n0 + half * 128;
        __half* wdst = g_w + (size_t)o * IN_DIM + n0 + half * 128;
#pragma unroll
        for (int cc = 0; cc < 4; ++cc) {
            uint32_t r[32];
            TCGEN05_LD_32X32B_X32(
                r, tmem + lane_off + (uint32_t)(half * 128 + cc * 32));
            TCGEN05_WAIT_LD();
            __half2 hv[16];
#pragma unroll
            for (int q = 0; q < 8; ++q) {
                float4 w = *(const float4*)(wsrc + cc * 32 + q * 4);
                hv[2 * q].x     = __float2half_rn(__uint_as_float(r[4 * q + 0]) + w.x);
                hv[2 * q].y     = __float2half_rn(__uint_as_float(r[4 * q + 1]) + w.y);
                hv[2 * q + 1].x = __float2half_rn(__uint_as_float(r[4 * q + 2]) + w.z);
                hv[2 * q + 1].y = __float2half_rn(__uint_as_float(r[4 * q + 3]) + w.w);
            }
            uint4* dst = (uint4*)(wdst + cc * 32);
            const uint4* src = (const uint4*)hv;
#pragma unroll
            for (int q = 0; q < 4; ++q) dst[q] = src[q];
        }
        TCGEN05_FENCE_BEFORE();
    }
    __syncthreads();
    if (wid == 0) TCGEN05_DEALLOC(tmem, 256);
#else
    (void)W_org; (void)map_ap; (void)map_qt;
#endif
}

// ============================================================================
// Main GEMM (tcgen05, cg1): 256x256 tile, single fp16 product, TMA pipeline.
// Byte-identical logic to the 485.9us winner (at its LTS-cap floor).
// ============================================================================
__global__ __launch_bounds__(256, 1)
void gemm_tc_kernel(float* __restrict__ out,
                    const __grid_constant__ CUtensorMap mx1,
                    const __grid_constant__ CUtensorMap mw) {
#if HAS_TC
    extern __shared__ char smem[];
    const uint32_t smem_base = smem_to_u32(smem);
    const int tid = threadIdx.x;
    const int wid = tid >> 5;
    const int lid = tid & 31;
    const int m0 = blockIdx.y * TILE_M;
    const int n0 = blockIdx.x * TILE_N;

    const uint32_t MB_FULLA  = smem_base + 0;
    const uint32_t MB_FULLB  = smem_base + 32;
    const uint32_t MB_EMPTYA = smem_base + 56;
    const uint32_t MB_EMPTYB = smem_base + 88;
    const uint32_t MB_DONE   = smem_base + 112;

    if (wid == 0) {
        TCGEN05_ALLOC(smem_base + 128, 512);
        TCGEN05_RELINQ();
    }
    if (tid == 0) {
#pragma unroll
        for (int s = 0; s < NSA; ++s) { MBARRIER_INIT(MB_FULLA + 8 * s, 1);
                                        MBARRIER_INIT(MB_EMPTYA + 8 * s, 1); }
#pragma unroll
        for (int s = 0; s < NSB; ++s) { MBARRIER_INIT(MB_FULLB + 8 * s, 1);
                                        MBARRIER_INIT(MB_EMPTYB + 8 * s, 1); }
        MBARRIER_INIT(MB_DONE, 1);
    }
    __syncthreads();

    uint32_t tmem;
    asm volatile("ld.shared.b32 %0, [%1];" : "=r"(tmem) : "r"(smem_base + 128));

    if (tid == 32) {
        for (int g = 0; g < NKG; ++g) {
            const int cx = g * 64;
            {
                const int s = g & (NSA - 1);
                MBARRIER_WAIT_PARITY(MB_EMPTYA + 8 * s, ((g >> 2) & 1) ^ 1);
                MBARRIER_EXPECT_TX(MB_FULLA + 8 * s, TILE_BYTES);
                tma_2d(&mx1, smem_base + SMEM_A0 + s * TILE_BYTES,
                       cx, m0, MB_FULLA + 8 * s);
            }
            {
                const int s = g % NSB;
                MBARRIER_WAIT_PARITY(MB_EMPTYB + 8 * s, ((g / NSB) & 1) ^ 1);
                MBARRIER_EXPECT_TX(MB_FULLB + 8 * s, TILE_BYTES);
                tma_2d(&mw, smem_base + SMEM_B0 + s * TILE_BYTES,
                       cx, n0, MB_FULLB + 8 * s);
            }
        }
    } else if (tid == 0) {
        for (int g = 0; g < NKG; ++g) {
            const int sa = g & (NSA - 1);
            const int sb = g % NSB;

            const uint32_t saddr = smem_base + SMEM_A0 + sa * TILE_BYTES;
            const uint64_t a0 = MAKE_SMEM_DESC(saddr);
            const uint64_t a1 = MAKE_SMEM_DESC(saddr + 16384);
            const uint64_t bd = MAKE_SMEM_DESC(smem_base + SMEM_B0 + sb * TILE_BYTES);

            MBARRIER_WAIT_PARITY(MB_FULLA + 8 * sa, (g >> 2) & 1);
            MBARRIER_WAIT_PARITY(MB_FULLB + 8 * sb, (g / NSB) & 1);
#pragma unroll
            for (int k = 0; k < 4; ++k) {
                uint32_t en = (g > 0 || k > 0) ? 1u : 0u;
                mma_f16_ss(tmem,       a0 + k * 2, bd + k * 2, GEMM_IDESC, en);
                mma_f16_ss(tmem + 256, a1 + k * 2, bd + k * 2, GEMM_IDESC, en);
            }
            TCGEN05_COMMIT(MB_EMPTYA + 8 * sa);
            TCGEN05_COMMIT(MB_EMPTYB + 8 * sb);
        }
        TCGEN05_COMMIT(MB_DONE);
    }

    MBARRIER_WAIT_PARITY(MB_DONE, 0);
    TCGEN05_FENCE_AFTER();
    {
        const int half = wid >> 2;
        const int sub  = wid & 3;
        const uint32_t lane_off = ((uint32_t)sub) << 21;
        const int m = m0 + half * 128 + sub * 32 + lid;
        float* orow = out + (size_t)m * OUT_DIM + n0;
#pragma unroll
        for (int cc = 0; cc < 8; ++cc) {
            uint32_t r[32];
            TCGEN05_LD_32X32B_X32(
                r, tmem + lane_off + (uint32_t)(half * 256 + cc * 32));
            TCGEN05_WAIT_LD();
            float* dst = orow + cc * 32;
#pragma unroll
            for (int q = 0; q < 8; ++q) {
                float4 v;
                v.x = __uint_as_float(r[4 * q + 0]);
                v.y = __uint_as_float(r[4 * q + 1]);
                v.z = __uint_as_float(r[4 * q + 2]);
                v.w = __uint_as_float(r[4 * q + 3]);
                ((float4*)dst)[q] = v;
            }
        }
        TCGEN05_FENCE_BEFORE();
    }

    __syncthreads();
    if (wid == 0) TCGEN05_DEALLOC(tmem, 512);
#else
    (void)out; (void)mx1; (void)mw;
#endif
}

// ============================================================================
// GEMM (mma.sync fallback) — grid-stride over 2048 tiles; early-exits when
// the tcgen05 path is live.
// ============================================================================
__global__ __launch_bounds__(512, 1)
void gemm_fb_kernel(float* __restrict__ out) {
    if (g_has_tc) return;

    extern __shared__ char smem[];
    const uint32_t smem_base = smem_to_u32(smem);
    const int tid = threadIdx.x;
    const int wid = tid >> 5;
    const int lid = tid & 31;
    const int wm = wid & 3;
    const int wn = wid >> 2;

    const int ar  = wm * 32 + (lid & 15);
    const int ca  = lid >> 4;
    const int axr = ar & 7;
    const int bn  = wn * 64 + (lid & 7) + ((lid >> 4) << 3);
    const int kb  = (lid >> 3) & 1;
    const int bxr = bn & 7;

    for (int tile = blockIdx.x; tile < FB_TILES; tile += gridDim.x) {
        const int m0 = (tile >> 4) * FB_TM;
        const int n0 = (tile & 15) * FB_TN;

        float acc[2][8][4];
#pragma unroll
        for (int i = 0; i < 2; ++i)
#pragma unroll
            for (int j = 0; j < 8; ++j)
#pragma unroll
                for (int k = 0; k < 4; ++k) acc[i][j][k] = 0.f;

        auto load_chunk = [&](int c) {
            const int st = c & 3;
            const int k0 = c << 6;
            const __half* Ab = g_x1 + (size_t)m0 * IN_DIM + k0;
            const __half* Bb = g_w  + (size_t)n0 * IN_DIM + k0;
            const uint32_t sa = smem_base + st * FB_STAGE;
            const uint32_t sb = sa + FB_A_BYTES;
#pragma unroll
            for (int it = 0; it < 2; ++it) {
                int i = tid + it * 512;
                int row = i >> 3, j = i & 7;
                uint32_t dst = sa + row * 128 + ((uint32_t)(j ^ (row & 7)) << 4);
                cp_async16(dst, Ab + (size_t)row * IN_DIM + j * 8);
            }
#pragma unroll
            for (int it = 0; it < 4; ++it) {
                int i = tid + it * 512;
                int row = i >> 3, j = i & 7;
                uint32_t dst = sb + row * 128 + ((uint32_t)(j ^ (row & 7)) << 4);
                cp_async16(dst, Bb + (size_t)row * IN_DIM + j * 8);
            }
            CP_COMMIT();
        };

        load_chunk(0);
        load_chunk(1);
        load_chunk(2);

        for (int c = 0; c < FB_NCH; ++c) {
            const int rem = FB_NCH - 1 - c;
            if (rem >= 2)      CP_WAIT(2);
            else if (rem == 1) CP_WAIT(1);
            else               CP_WAIT(0);
            __syncthreads();
            if (c + 3 < FB_NCH) load_chunk(c + 3);

            const uint32_t sa = smem_base + (c & 3) * FB_STAGE;
            const uint32_t sb = sa + FB_A_BYTES;

#pragma unroll
            for (int s = 0; s < 4; ++s) {
                uint32_t a[2][4];
#pragma unroll
                for (int mb = 0; mb < 2; ++mb) {
                    uint32_t addr = sa + (ar + mb * 16) * 128
                                  + ((uint32_t)(((s << 1) + ca) ^ axr) << 4);
                    ldsm_x4(a[mb], addr);
                }
#pragma unroll
                for (int nb = 0; nb < 4; ++nb) {
                    uint32_t b[4];
                    uint32_t addr = sb + (bn + nb * 16) * 128
                                  + ((uint32_t)(((s << 1) + kb) ^ bxr) << 4);
                    ldsm_x4(b, addr);
#pragma unroll
                    for (int mb = 0; mb < 2; ++mb) {
                        mma16816f16(acc[mb][nb * 2 + 0], a[mb], b + 0);
                        mma16816f16(acc[mb][nb * 2 + 1], a[mb], b + 2);
                    }
                }
            }
        }
        __syncthreads();   // smem reuse safety before next tile's loads

#pragma unroll
        for (int mb = 0; mb < 2; ++mb) {
            const int r0 = m0 + wm * 32 + mb * 16 + (lid >> 2);
#pragma unroll
            for (int nb8 = 0; nb8 < 8; ++nb8) {
                const int col = n0 + wn * 64 + nb8 * 8 + (lid & 3) * 2;
                float2 v0; v0.x = acc[mb][nb8][0]; v0.y = acc[mb][nb8][1];
                float2 v1; v1.x = acc[mb][nb8][2]; v1.y = acc[mb][nb8][3];
                *(float2*)(out + (size_t)r0 * OUT_DIM + col)       = v0;
                *(float2*)(out + (size_t)(r0 + 8) * OUT_DIM + col) = v1;
            }
        }
    }
}

// ============================================================================
// Host: tensor-map construction via driver entry point (no -lcuda link)
// ============================================================================
typedef CUresult (*PFN_tmeTiled)(
    CUtensorMap*, CUtensorMapDataType, unsigned int, void*,
    const unsigned long long*, const unsigned long long*,
    const unsigned int*, const unsigned int*,
    CUtensorMapInterleave, CUtensorMapSwizzle,
    CUtensorMapL2promotion, CUtensorMapFloatOOBfill);

static void make_map(PFN_tmeTiled enc, CUtensorMap* m, void* base,
                     unsigned long long cols, unsigned long long rows,
                     unsigned int box_h) {
    unsigned long long dims[2]    = {cols, rows};
    unsigned long long strides[1] = {cols * sizeof(__half)};
    unsigned int box[2]  = {64, box_h};
    unsigned int es[2]   = {1, 1};
    enc(m, CU_TENSOR_MAP_DATA_TYPE_FLOAT16, 2, base, dims, strides, box, es,
        CU_TENSOR_MAP_INTERLEAVE_NONE, CU_TENSOR_MAP_SWIZZLE_128B,
        CU_TENSOR_MAP_L2_PROMOTION_L2_128B, CU_TENSOR_MAP_FLOAT_OOB_FILL_NONE);
}

extern "C" void kernel_launch(void* const* d_in, const int* in_sizes, int n_in,
                              void* d_out, int out_size) {
    (void)in_sizes; (void)n_in; (void)out_size;
    const float* x      = (const float*)d_in[0];
    const float* W_org  = (const float*)d_in[1];
    const float* q_w    = (const float*)d_in[2];
    const float* p_w    = (const float*)d_in[3];
    const float* lam    = (const float*)d_in[4];
    const float* bq_w   = (const float*)d_in[5];
    const float* bp_w   = (const float*)d_in[6];
    const float* blam   = (const float*)d_in[7];
    float* out = (float*)d_out;

    cudaFuncSetAttribute(gemm_tc_kernel,
                         cudaFuncAttributeMaxDynamicSharedMemorySize, SMEM_TC);
    cudaFuncSetAttribute(fold_tc_kernel,
                         cudaFuncAttributeMaxDynamicSharedMemorySize, SMEM_FOLD);
    cudaFuncSetAttribute(gemm_fb_kernel,
                         cudaFuncAttributeMaxDynamicSharedMemorySize, SMEM_FB);

    void* fn = nullptr;
    cudaDriverEntryPointQueryResult qst;
    cudaGetDriverEntryPoint("cuTensorMapEncodeTiled", &fn,
                            cudaEnableDefault, &qst);
    PFN_tmeTiled enc = (PFN_tmeTiled)fn;

    void *p_x1, *p_w_, *p_ap, *p_qt;
    cudaGetSymbolAddress(&p_x1, g_x1);
    cudaGetSymbolAddress(&p_w_, g_w);
    cudaGetSymbolAddress(&p_ap, g_ap16);
    cudaGetSymbolAddress(&p_qt, g_qt16);

    CUtensorMap mx1{}, mw{}, map_ap{}, map_qt{};
    make_map(enc, &mx1, p_x1, IN_DIM, M_TOTAL, 256);
    make_map(enc, &mw,  p_w_, IN_DIM, OUT_DIM, 256);
    make_map(enc, &map_ap, p_ap, 128, OUT_DIM, 128);   // A' tile: 128 rows
    make_map(enc, &map_qt, p_qt, 128, IN_DIM, 256);    // Qt tile: 256 rows

    build_aprime_kernel<<<(OUT_DIM * 2 * RANK) / 256, 256>>>(p_w, lam, bp_w, blam);
    transpose_q_kernel<<<IN_DIM / 64, 256>>>(q_w, bq_w);
    fold_w_kernel<<<OUT_DIM / 16, 256>>>(W_org, q_w, bq_w);
    fold_tc_kernel<<<dim3(IN_DIM / 256, OUT_DIM / 128), 256, SMEM_FOLD>>>(
        W_org, map_ap, map_qt);
    split_x_kernel<<<(int)(((size_t)M_TOTAL * IN_DIM / 4) / 256), 256>>>(
        (const float4*)x);

    gemm_tc_kernel<<<dim3(OUT_DIM / TILE_N, M_TOTAL / TILE_M), 256, SMEM_TC>>>(
        out, mx1, mw);
    gemm_fb_kernel<<<512, 512, SMEM_FB>>>(out);
}